// round 15
// baseline (speedup 1.0000x reference)
#include <cuda_runtime.h>

#define EPS 1e-8f

// Scratch (no allocation allowed).
__device__ float g_h1[256 * 1024];
__device__ float g_h2[256 * 1024];
__device__ float g_acc[256 * 1024];   // single cross-CTA accumulator plane;
                                      // zero-invariant: zero at load, re-zeroed
                                      // by each combine after reading.
__device__ float g_Sx[256];
__device__ float g_Sh1[256];
__device__ float g_Sh2[256];
__device__ float g_Sw1[1024];
__device__ float g_Sw2[1024];
__device__ float g_Sw3[128];

// ---------------------------------------------------------------------------
// Warp-per-row row-sum: one warp sums one 1024-float row (8x LDG.128 + shfl).
__device__ __forceinline__ void warp_rowsum(const float* __restrict__ A,
                                            float* __restrict__ S,
                                            int row, int lane)
{
    const float4* a = reinterpret_cast<const float4*>(A + ((size_t)row << 10));
    float s = 0.0f;
#pragma unroll
    for (int i = 0; i < 8; i++) {
        float4 v = a[lane + 32 * i];
        s += (v.x + v.y) + (v.z + v.w);
    }
#pragma unroll
    for (int o = 16; o > 0; o >>= 1) s += __shfl_xor_sync(0xFFFFFFFFu, s, o);
    if (lane == 0) S[row] = s;
}

// ---------------------------------------------------------------------------
// Tversky tile body (R11/R14 proven: BM=128, BN=128, DK=16, 512 threads,
// TM=8 x TN=4, double-buffered smem, one barrier/tile). Epilogue: atomicAdd
// into the single accumulator plane (replaces NZ private planes).
__device__ __forceinline__ void tversky_tile_body(
    const float* __restrict__ X, const float* __restrict__ W,
    float* __restrict__ accb, int O, int D,
    int m0, int n0, int z, int kspan)
{
    constexpr int DK = 16, TM = 8, TN = 4;
    constexpr int XSTR = DK + 4;          // 20 floats
    constexpr int WSTR = 128 + 4;         // 132 floats

    const int tid = threadIdx.x;
    const int tx  = tid & 31;
    const int ty  = tid >> 5;
    const int k0  = z * kspan;

    __shared__ __align__(16) float Xs[2][128][XSTR];
    __shared__ __align__(16) float Ws[2][DK][WSTR];

    const int lr = tid >> 2, lq = tid & 3;

    const float4* Xg = reinterpret_cast<const float4*>(X + (size_t)(m0 + lr) * D + k0) + lq;
    const float4* Wg = reinterpret_cast<const float4*>(W + (size_t)(n0 + lr) * D + k0) + lq;

    float acc[TM][TN];
#pragma unroll
    for (int i = 0; i < TM; i++)
#pragma unroll
        for (int j = 0; j < TN; j++) acc[i][j] = 0.0f;

    const int ntiles = kspan / DK;

    float4 xv = Xg[0];
    float4 wv = Wg[0];
    *reinterpret_cast<float4*>(&Xs[0][lr][lq * 4]) = xv;
#pragma unroll
    for (int c = 0; c < 4; c++)
        Ws[0][lq * 4 + c][lr] = (&wv.x)[c];
    __syncthreads();

    for (int t = 0; t < ntiles; t++) {
        const int buf = t & 1;
        const bool more = (t + 1 < ntiles);

        if (more) {
            const int off = (t + 1) * (DK / 4);
            xv = Xg[off];
            wv = Wg[off];
        }

#pragma unroll
        for (int kk = 0; kk < DK; kk += 4) {
            float4 xk[TM];
#pragma unroll
            for (int i = 0; i < TM; i++)
                xk[i] = *reinterpret_cast<const float4*>(&Xs[buf][ty * TM + i][kk]);
            float4 wk[4];
#pragma unroll
            for (int c = 0; c < 4; c++)
                wk[c] = *reinterpret_cast<const float4*>(&Ws[buf][kk + c][tx * TN]);
#pragma unroll
            for (int c = 0; c < 4; c++) {
#pragma unroll
                for (int i = 0; i < TM; i++) {
                    const float xi = (&xk[i].x)[c];
                    acc[i][0] += fminf(xi, wk[c].x);
                    acc[i][1] += fminf(xi, wk[c].y);
                    acc[i][2] += fminf(xi, wk[c].z);
                    acc[i][3] += fminf(xi, wk[c].w);
                }
            }
        }

        if (more) {
            const int nbuf = buf ^ 1;
            *reinterpret_cast<float4*>(&Xs[nbuf][lr][lq * 4]) = xv;
#pragma unroll
            for (int c = 0; c < 4; c++)
                Ws[nbuf][lq * 4 + c][lr] = (&wv.x)[c];
            __syncthreads();
        }
    }

    // Epilogue: accumulate into the shared plane (z-splits collide benignly).
    const int row = m0 + ty * TM;
    const int col = n0 + tx * TN;
#pragma unroll
    for (int i = 0; i < TM; i++)
#pragma unroll
        for (int j = 0; j < TN; j++)
            atomicAdd(accb + (size_t)(row + i) * O + col + j, acc[i][j]);
}

// ---------------------------------------------------------------------------
// Layer-1 fused kernel: 1D grid of 148 CTAs.
//  CTAs 0..127  : tversky tiles (decode = former dim3(8,2,8) grid).
//  CTAs 128..147: all 2432 static row-sums (x, W1, W2, W3), warp-per-row.
__global__ __launch_bounds__(512)
void tversky_l1_fused_kernel(const float* __restrict__ X,
                             const float* __restrict__ W1,
                             const float* __restrict__ W2,
                             const float* __restrict__ W3,
                             float* __restrict__ accb,
                             float* __restrict__ Sx,  float* __restrict__ Sw1,
                             float* __restrict__ Sw2, float* __restrict__ Sw3,
                             int O, int D, int kspan)
{
    const int bid = blockIdx.x;
    if (bid < 128) {
        const int gx = bid & 7;
        const int gy = (bid >> 3) & 1;
        const int gz = bid >> 4;
        tversky_tile_body(X, W1, accb, O, D, gy * 128, gx * 128, gz, kspan);
    } else {
        const int lane = threadIdx.x & 31;
        const int gw   = (bid - 128) * 16 + (threadIdx.x >> 5);
        for (int r = gw; r < 2432; r += 320) {
            if (r < 256)       warp_rowsum(X,  Sx,  r,        lane);
            else if (r < 1280) warp_rowsum(W1, Sw1, r - 256,  lane);
            else if (r < 2304) warp_rowsum(W2, Sw2, r - 1280, lane);
            else               warp_rowsum(W3, Sw3, r - 2304, lane);
        }
    }
}

// ---------------------------------------------------------------------------
// Plain tile kernel for layers 2 and 3.
__global__ __launch_bounds__(512)
void tversky_part_kernel(const float* __restrict__ X,
                         const float* __restrict__ W,
                         float* __restrict__ accb,
                         int O, int D, int kspan)
{
    tversky_tile_body(X, W, accb, O, D,
                      blockIdx.y * 128, blockIdx.x * 128, blockIdx.z, kspan);
}

// ---------------------------------------------------------------------------
// Combine: read accumulator plane, RE-ZERO it, epilogue(+relu) + row-sum.
// One block per output row; 256 threads, 4 cols each (O=1024).
__global__ void combine_epi_rowsum_kernel(float* __restrict__ accb,
                                          const float* __restrict__ Sx,
                                          const float* __restrict__ Sw,
                                          float* __restrict__ h,
                                          float* __restrict__ Sh,
                                          int O)
{
    const int row = blockIdx.x;
    const int j0  = threadIdx.x * 4;
    const size_t base = (size_t)row * O + j0;

    float4 c = *reinterpret_cast<const float4*>(accb + base);
    *reinterpret_cast<float4*>(accb + base) = make_float4(0.f, 0.f, 0.f, 0.f);
    float4 sw = *reinterpret_cast<const float4*>(Sw + j0);
    const float sx = Sx[row];

    float4 o;
    o.x = fmaxf(c.x / (0.5f * (sx + sw.x) + EPS), 0.0f);
    o.y = fmaxf(c.y / (0.5f * (sx + sw.y) + EPS), 0.0f);
    o.z = fmaxf(c.z / (0.5f * (sx + sw.z) + EPS), 0.0f);
    o.w = fmaxf(c.w / (0.5f * (sx + sw.w) + EPS), 0.0f);
    *reinterpret_cast<float4*>(h + base) = o;

    float s = (o.x + o.y) + (o.z + o.w);
#pragma unroll
    for (int off = 16; off > 0; off >>= 1) s += __shfl_xor_sync(0xFFFFFFFFu, s, off);
    __shared__ float ws[8];
    const int lane = threadIdx.x & 31, w = threadIdx.x >> 5;
    if (lane == 0) ws[w] = s;
    __syncthreads();
    if (w == 0) {
        s = (lane < 8) ? ws[lane] : 0.0f;
#pragma unroll
        for (int off = 4; off > 0; off >>= 1) s += __shfl_xor_sync(0xFFFFFFFFu, s, off);
        if (lane == 0) Sh[row] = s;
    }
}

// Final combine: read + re-zero, epilogue (no relu, no rowsum).
__global__ void combine_final_kernel(float* __restrict__ accb,
                                     const float* __restrict__ Sx,
                                     const float* __restrict__ Sw,
                                     float* __restrict__ out,
                                     int O, int BO)
{
    int i = blockIdx.x * blockDim.x + threadIdx.x;
    if (i >= BO) return;
    float c = accb[i];
    accb[i] = 0.0f;
    const int m = i / O, n = i % O;
    out[i] = c / (0.5f * (Sx[m] + Sw[n]) + EPS);
}

// ---------------------------------------------------------------------------
extern "C" void kernel_launch(void* const* d_in, const int* in_sizes, int n_in,
                              void* d_out, int out_size)
{
    const float* x  = (const float*)d_in[0];   // [256, 1024]
    const float* W1 = (const float*)d_in[1];   // [1024, 1024]
    const float* W2 = (const float*)d_in[2];   // [1024, 1024]
    const float* W3 = (const float*)d_in[3];   // [128, 1024]
    float* out = (float*)d_out;                // [256, 128]

    const int B = 256, H = 1024, C = 128, D = 1024;

    float *h1, *h2, *acc, *Sx, *Sh1, *Sh2, *Sw1, *Sw2, *Sw3;
    cudaGetSymbolAddress((void**)&h1,  g_h1);
    cudaGetSymbolAddress((void**)&h2,  g_h2);
    cudaGetSymbolAddress((void**)&acc, g_acc);
    cudaGetSymbolAddress((void**)&Sx,  g_Sx);
    cudaGetSymbolAddress((void**)&Sh1, g_Sh1);
    cudaGetSymbolAddress((void**)&Sh2, g_Sh2);
    cudaGetSymbolAddress((void**)&Sw1, g_Sw1);
    cudaGetSymbolAddress((void**)&Sw2, g_Sw2);
    cudaGetSymbolAddress((void**)&Sw3, g_Sw3);

    // Layer 1 fused with ALL static row-sums: 148 CTAs (128 tversky + 20 rowsum).
    tversky_l1_fused_kernel<<<148, 512>>>(x, W1, W2, W3, acc,
                                          Sx, Sw1, Sw2, Sw3, H, D, D / 8);
    combine_epi_rowsum_kernel<<<B, 256>>>(acc, Sx, Sw1, h1, Sh1, H);

    // Layer 2: h1 vs W2, split-K=8 (grid 8x2x8 = 128 CTAs), fused combine.
    {
        dim3 grid(H / 128, B / 128, 8);
        tversky_part_kernel<<<grid, 512>>>(h1, W2, acc, H, H, H / 8);
        combine_epi_rowsum_kernel<<<B, 256>>>(acc, Sh1, Sw2, h2, Sh2, H);
    }
    // Layer 3: h2 vs W3, split-K=64 (grid 1x2x64 = 128 CTAs), final combine.
    {
        const int NZ = 64;
        dim3 grid(C / 128, B / 128, NZ);
        tversky_part_kernel<<<grid, 512>>>(h2, W3, acc, C, H, H / NZ);
        combine_final_kernel<<<(B * C + 255) / 256, 256>>>(acc, Sh2, Sw3, out, C, B * C);
    }
}

// round 16
// speedup vs baseline: 1.2647x; 1.2647x over previous
#include <cuda_runtime.h>

#define EPS 1e-8f

// Scratch (no allocation allowed).
__device__ float g_h1[256 * 1024];
__device__ float g_h2[256 * 1024];
__device__ float g_pC[8 * 256 * 1024];   // 8 planes L1/L2; 64*256*128 for L3
__device__ float g_Sx[256];
__device__ float g_Sh1[256];
__device__ float g_Sh2[256];
__device__ float g_Sw1[1024];
__device__ float g_Sw2[1024];
__device__ float g_Sw3[128];

// ---------------------------------------------------------------------------
// Warp-per-row row-sum: one warp sums one 1024-float row (8x LDG.128 + shfl).
__device__ __forceinline__ void warp_rowsum(const float* __restrict__ A,
                                            float* __restrict__ S,
                                            int row, int lane)
{
    const float4* a = reinterpret_cast<const float4*>(A + ((size_t)row << 10));
    float s = 0.0f;
#pragma unroll
    for (int i = 0; i < 8; i++) {
        float4 v = a[lane + 32 * i];
        s += (v.x + v.y) + (v.z + v.w);
    }
#pragma unroll
    for (int o = 16; o > 0; o >>= 1) s += __shfl_xor_sync(0xFFFFFFFFu, s, o);
    if (lane == 0) S[row] = s;
}

// ---------------------------------------------------------------------------
// Tversky tile body (R11/R14 proven: BM=128, BN=128, DK=16, 512 threads,
// TM=8 x TN=4, double-buffered smem, one barrier/tile, STG.128 plane stores).
__device__ __forceinline__ void tversky_tile_body(
    const float* __restrict__ X, const float* __restrict__ W,
    float* __restrict__ pC, int B, int O, int D,
    int m0, int n0, int z, int kspan)
{
    constexpr int DK = 16, TM = 8, TN = 4;
    constexpr int XSTR = DK + 4;          // 20 floats
    constexpr int WSTR = 128 + 4;         // 132 floats

    const int tid = threadIdx.x;
    const int tx  = tid & 31;
    const int ty  = tid >> 5;
    const int k0  = z * kspan;

    __shared__ __align__(16) float Xs[2][128][XSTR];
    __shared__ __align__(16) float Ws[2][DK][WSTR];

    const int lr = tid >> 2, lq = tid & 3;

    const float4* Xg = reinterpret_cast<const float4*>(X + (size_t)(m0 + lr) * D + k0) + lq;
    const float4* Wg = reinterpret_cast<const float4*>(W + (size_t)(n0 + lr) * D + k0) + lq;

    float acc[TM][TN];
#pragma unroll
    for (int i = 0; i < TM; i++)
#pragma unroll
        for (int j = 0; j < TN; j++) acc[i][j] = 0.0f;

    const int ntiles = kspan / DK;

    float4 xv = Xg[0];
    float4 wv = Wg[0];
    *reinterpret_cast<float4*>(&Xs[0][lr][lq * 4]) = xv;
#pragma unroll
    for (int c = 0; c < 4; c++)
        Ws[0][lq * 4 + c][lr] = (&wv.x)[c];
    __syncthreads();

    for (int t = 0; t < ntiles; t++) {
        const int buf = t & 1;
        const bool more = (t + 1 < ntiles);

        if (more) {
            const int off = (t + 1) * (DK / 4);
            xv = Xg[off];
            wv = Wg[off];
        }

#pragma unroll
        for (int kk = 0; kk < DK; kk += 4) {
            float4 xk[TM];
#pragma unroll
            for (int i = 0; i < TM; i++)
                xk[i] = *reinterpret_cast<const float4*>(&Xs[buf][ty * TM + i][kk]);
            float4 wk[4];
#pragma unroll
            for (int c = 0; c < 4; c++)
                wk[c] = *reinterpret_cast<const float4*>(&Ws[buf][kk + c][tx * TN]);
#pragma unroll
            for (int c = 0; c < 4; c++) {
#pragma unroll
                for (int i = 0; i < TM; i++) {
                    const float xi = (&xk[i].x)[c];
                    acc[i][0] += fminf(xi, wk[c].x);
                    acc[i][1] += fminf(xi, wk[c].y);
                    acc[i][2] += fminf(xi, wk[c].z);
                    acc[i][3] += fminf(xi, wk[c].w);
                }
            }
        }

        if (more) {
            const int nbuf = buf ^ 1;
            *reinterpret_cast<float4*>(&Xs[nbuf][lr][lq * 4]) = xv;
#pragma unroll
            for (int c = 0; c < 4; c++)
                Ws[nbuf][lq * 4 + c][lr] = (&wv.x)[c];
            __syncthreads();
        }
    }

    const size_t zb = (size_t)z * B * O;
#pragma unroll
    for (int i = 0; i < TM; i++) {
        float4 o4;
        o4.x = acc[i][0]; o4.y = acc[i][1]; o4.z = acc[i][2]; o4.w = acc[i][3];
        *reinterpret_cast<float4*>(pC + zb + (size_t)(m0 + ty * TM + i) * O
                                   + (n0 + tx * TN)) = o4;
    }
}

// ---------------------------------------------------------------------------
// Layer-1 fused kernel: 1D grid of 148 CTAs (R14 proven).
__global__ __launch_bounds__(512)
void tversky_l1_fused_kernel(const float* __restrict__ X,
                             const float* __restrict__ W1,
                             const float* __restrict__ W2,
                             const float* __restrict__ W3,
                             float* __restrict__ pC,
                             float* __restrict__ Sx,  float* __restrict__ Sw1,
                             float* __restrict__ Sw2, float* __restrict__ Sw3,
                             int B, int O, int D, int kspan)
{
    const int bid = blockIdx.x;
    if (bid < 128) {
        const int gx = bid & 7;
        const int gy = (bid >> 3) & 1;
        const int gz = bid >> 4;
        tversky_tile_body(X, W1, pC, B, O, D, gy * 128, gx * 128, gz, kspan);
    } else {
        const int lane = threadIdx.x & 31;
        const int gw   = (bid - 128) * 16 + (threadIdx.x >> 5);
        for (int r = gw; r < 2432; r += 320) {
            if (r < 256)       warp_rowsum(X,  Sx,  r,        lane);
            else if (r < 1280) warp_rowsum(W1, Sw1, r - 256,  lane);
            else if (r < 2304) warp_rowsum(W2, Sw2, r - 1280, lane);
            else               warp_rowsum(W3, Sw3, r - 2304, lane);
        }
    }
}

// ---------------------------------------------------------------------------
// Plain tile kernel for layers 2 and 3 (R14 proven).
__global__ __launch_bounds__(512)
void tversky_part_kernel(const float* __restrict__ X,
                         const float* __restrict__ W,
                         float* __restrict__ pC,
                         int B, int O, int D, int kspan)
{
    tversky_tile_body(X, W, pC, B, O, D,
                      blockIdx.y * 128, blockIdx.x * 128, blockIdx.z, kspan);
}

// ---------------------------------------------------------------------------
// Combine 8 partial planes + epilogue(+relu) + row-sum, PARALLELIZED over z:
// 512 threads per row; half 0 sums planes 0-3, half 1 sums planes 4-7
// (serial chain 8 -> 4, thread count 2x), smem join, then epilogue + rowsum.
__global__ __launch_bounds__(512)
void combine_epi_rowsum_kernel(const float* __restrict__ pC,
                               const float* __restrict__ Sx,
                               const float* __restrict__ Sw,
                               float* __restrict__ h,
                               float* __restrict__ Sh,
                               int B, int O)
{
    const int row  = blockIdx.x;
    const int tid  = threadIdx.x;
    const int half = tid >> 8;            // 0 or 1
    const int t    = tid & 255;
    const int j0   = t * 4;
    const size_t plane = (size_t)B * O;
    const size_t base  = (size_t)row * O + j0;

    float cx = 0.f, cy = 0.f, cz = 0.f, cw = 0.f;
#pragma unroll
    for (int q = 0; q < 4; q++) {
        const int z = half * 4 + q;
        float4 c = *reinterpret_cast<const float4*>(pC + (size_t)z * plane + base);
        cx += c.x; cy += c.y; cz += c.z; cw += c.w;
    }

    __shared__ __align__(16) float4 part[256];
    if (half == 1) part[t] = make_float4(cx, cy, cz, cw);
    __syncthreads();

    float s = 0.0f;
    if (half == 0) {
        float4 p = part[t];
        cx += p.x; cy += p.y; cz += p.z; cw += p.w;

        float4 sw = *reinterpret_cast<const float4*>(Sw + j0);
        const float sx = Sx[row];
        float4 o;
        o.x = fmaxf(cx / (0.5f * (sx + sw.x) + EPS), 0.0f);
        o.y = fmaxf(cy / (0.5f * (sx + sw.y) + EPS), 0.0f);
        o.z = fmaxf(cz / (0.5f * (sx + sw.z) + EPS), 0.0f);
        o.w = fmaxf(cw / (0.5f * (sx + sw.w) + EPS), 0.0f);
        *reinterpret_cast<float4*>(h + base) = o;
        s = (o.x + o.y) + (o.z + o.w);
    }

    // Row-sum over the 8 warps of half 0.
#pragma unroll
    for (int off = 16; off > 0; off >>= 1) s += __shfl_xor_sync(0xFFFFFFFFu, s, off);
    __shared__ float ws[8];
    const int lane = tid & 31, w = tid >> 5;
    if (half == 0 && lane == 0) ws[w] = s;
    __syncthreads();
    if (w == 0) {
        s = (lane < 8) ? ws[lane] : 0.0f;
#pragma unroll
        for (int off = 4; off > 0; off >>= 1) s += __shfl_xor_sync(0xFFFFFFFFu, s, off);
        if (lane == 0) Sh[row] = s;
    }
}

// ---------------------------------------------------------------------------
// Final combine, PARALLELIZED over z: 512 blocks x 256 threads.
// Thread = (output o, z-quarter zq): sums 16 of the 64 planes (unrolled),
// smem 4-way join, epilogue (no relu).
__global__ __launch_bounds__(256)
void combine_final_kernel(const float* __restrict__ pC,
                          const float* __restrict__ Sx,
                          const float* __restrict__ Sw,
                          float* __restrict__ out,
                          int O, int BO)
{
    const int tid = threadIdx.x;
    const int ol  = tid & 63;             // output within block
    const int zq  = tid >> 6;             // z-quarter 0..3
    const int i   = blockIdx.x * 64 + ol; // global output index

    float c = 0.0f;
#pragma unroll
    for (int q = 0; q < 16; q++)
        c += pC[(size_t)(zq * 16 + q) * BO + i];

    __shared__ float sm[256];
    sm[tid] = c;
    __syncthreads();
    if (tid < 64) {
        c = (sm[tid] + sm[tid + 64]) + (sm[tid + 128] + sm[tid + 192]);
        const int m = i / O, n = i % O;
        out[i] = c / (0.5f * (Sx[m] + Sw[n]) + EPS);
    }
}

// ---------------------------------------------------------------------------
extern "C" void kernel_launch(void* const* d_in, const int* in_sizes, int n_in,
                              void* d_out, int out_size)
{
    const float* x  = (const float*)d_in[0];   // [256, 1024]
    const float* W1 = (const float*)d_in[1];   // [1024, 1024]
    const float* W2 = (const float*)d_in[2];   // [1024, 1024]
    const float* W3 = (const float*)d_in[3];   // [128, 1024]
    float* out = (float*)d_out;                // [256, 128]

    const int B = 256, H = 1024, C = 128, D = 1024;

    float *h1, *h2, *pC, *Sx, *Sh1, *Sh2, *Sw1, *Sw2, *Sw3;
    cudaGetSymbolAddress((void**)&h1,  g_h1);
    cudaGetSymbolAddress((void**)&h2,  g_h2);
    cudaGetSymbolAddress((void**)&pC,  g_pC);
    cudaGetSymbolAddress((void**)&Sx,  g_Sx);
    cudaGetSymbolAddress((void**)&Sh1, g_Sh1);
    cudaGetSymbolAddress((void**)&Sh2, g_Sh2);
    cudaGetSymbolAddress((void**)&Sw1, g_Sw1);
    cudaGetSymbolAddress((void**)&Sw2, g_Sw2);
    cudaGetSymbolAddress((void**)&Sw3, g_Sw3);

    // Layer 1 fused with ALL static row-sums: 148 CTAs (128 tversky + 20 rowsum).
    tversky_l1_fused_kernel<<<148, 512>>>(x, W1, W2, W3, pC,
                                          Sx, Sw1, Sw2, Sw3, B, H, D, D / 8);
    combine_epi_rowsum_kernel<<<B, 512>>>(pC, Sx, Sw1, h1, Sh1, B, H);

    // Layer 2: h1 vs W2, split-K=8 (grid 8x2x8 = 128 CTAs), fused combine.
    {
        dim3 grid(H / 128, B / 128, 8);
        tversky_part_kernel<<<grid, 512>>>(h1, W2, pC, B, H, H, H / 8);
        combine_epi_rowsum_kernel<<<B, 512>>>(pC, Sh1, Sw2, h2, Sh2, B, H);
    }
    // Layer 3: h2 vs W3, split-K=64 (grid 1x2x64 = 128 CTAs), parallel combine.
    {
        const int NZ = 64;
        dim3 grid(C / 128, B / 128, NZ);
        tversky_part_kernel<<<grid, 512>>>(h2, W3, pC, B, C, H, H / NZ);
        combine_final_kernel<<<(B * C) / 64, 256>>>(pC, Sh2, Sw3, out, C, B * C);
    }
}